// round 10
// baseline (speedup 1.0000x reference)
#include <cuda_runtime.h>
#include <cstdint>

constexpr int N = 64, C = 256, S = 30, HW = 176;
constexpr int CSTR = S * HW, NSTR = C * CSTR;
constexpr int R = 8, TOPK = 10;
constexpr int H = 4;                      // hw per block (176/4 = 44 tiles)
constexpr int CI = 128, NIT = 2;          // channels per iteration
constexpr int SLOTS = CI + 2 * R;         // 144 (circular halo)
constexpr int P = 6;                      // pitch words: 4 hw + 2 pad, conflict-free
constexpr int SCH = 10, NCH = 3;          // s-chunks for load/compute overlap
constexpr int SMEMB = S * SLOTS * P * 4;  // 103680 B -> 2 blocks/SM

__device__ float d_g[R + 1];

// g[d] = (1/256)(1 + 2*sum_{k=1..127} e^{-k^2/2048} cos(pi k d/128) + e^{-8} cos(pi d))
__global__ void kinit() {
    const int d = blockIdx.x, t = threadIdx.x;
    const double PI = 3.14159265358979323846;
    double k = (double)(t + 1);
    double term = exp(-k * k / 2048.0) * cos(PI * k * (double)d / 128.0);
    if (t != 127) term *= 2.0;            // Nyquist (k=128) counted once
    __shared__ double red[4];
    #pragma unroll
    for (int o = 16; o; o >>= 1) term += __shfl_down_sync(0xffffffffu, term, o);
    if ((t & 31) == 0) red[t >> 5] = term;
    __syncthreads();
    if (t == 0) d_g[d] = (float)((1.0 + red[0] + red[1] + red[2] + red[3]) / 256.0);
}

__global__ void __launch_bounds__(256, 2)
kfused(const float* __restrict__ seqs, const float* __restrict__ flogit,
       float* __restrict__ out) {
    extern __shared__ float sm[];
    const int hw0 = blockIdx.x * H;
    const int n   = blockIdx.y;
    const int tid = threadIdx.x;
    const int hw  = tid & 3;
    const int cg  = tid >> 2;             // 0..63 -> channels 2cg, 2cg+1
    const int w0  = 2 * cg;               // window base slot
    const float alpha = 1.0f / (1.0f + expf(-flogit[0]));

    float g[R + 1];
    #pragma unroll
    for (int d = 0; d <= R; ++d) g[d] = d_g[d];

    #pragma unroll 1
    for (int it = 0; it < NIT; ++it) {
        const int cb = it * CI + C - R;   // slot -> channel (cb+slot)&255

        // Issue all 3 s-chunk load groups (8B cp.asyncs: pitch-6 rows are
        // only 8B-aligned, not 16B)
        #pragma unroll
        for (int ck = 0; ck < NCH; ++ck) {
            for (int i = tid; i < SLOTS * SCH * 2; i += 256) {
                int q = i & 1, r = i >> 1;
                int sl = r / SLOTS, slot = r - sl * SLOTS;
                int s = ck * SCH + sl;
                int c = (cb + slot) & 255;
                const float* src = seqs + (size_t)n * NSTR + (size_t)c * CSTR
                                   + s * HW + hw0 + q * 2;
                uint32_t dst = (uint32_t)__cvta_generic_to_shared(
                    sm + (s * SLOTS + slot) * P + q * 2);
                asm volatile("cp.async.ca.shared.global [%0],[%1],8;"
                             :: "r"(dst), "l"(src));
            }
            asm volatile("cp.async.commit_group;" ::: "memory");
        }

        float sc[2][S], top[2][TOPK];
        #pragma unroll
        for (int ch = 0; ch < 2; ++ch)
            #pragma unroll
            for (int i = 0; i < TOPK; ++i) top[ch][i] = -1.0f;

        // Compute chunk k while chunk k+1 streams in
        #pragma unroll
        for (int ck = 0; ck < NCH; ++ck) {
            if (ck == 0)      asm volatile("cp.async.wait_group 2;" ::: "memory");
            else if (ck == 1) asm volatile("cp.async.wait_group 1;" ::: "memory");
            else              asm volatile("cp.async.wait_group 0;" ::: "memory");
            __syncthreads();

            #pragma unroll
            for (int j = 0; j < SCH; ++j) {
                const int s = ck * SCH + j;
                const float* b = sm + (s * SLOTS + w0) * P + hw;
                float w[2 * R + 2];
                #pragma unroll
                for (int u = 0; u < 2 * R + 2; ++u) w[u] = b[u * P];
                #pragma unroll
                for (int ch = 0; ch < 2; ++ch) {
                    const float x = w[ch + R];
                    float acc = g[0] * x;
                    #pragma unroll
                    for (int d = 1; d <= R; ++d)
                        acc = fmaf(g[d], w[ch + R - d] + w[ch + R + d], acc);
                    const float sv = __fdividef(fabsf(acc), fabsf(acc - x) + 1e-6f);
                    sc[ch][s] = sv;
                    float cr = sv;             // triangular insertion chain
                    #pragma unroll
                    for (int i = 0; i < TOPK; ++i) {
                        if (i <= s) {
                            float m = fmaxf(top[ch][i], cr);
                            cr      = fminf(top[ch][i], cr);
                            top[ch][i] = m;
                        }
                    }
                }
            }
        }

        // Threshold + stable-tie selection + max pool + fused output
        #pragma unroll
        for (int ch = 0; ch < 2; ++ch) {
            const float thr = top[ch][TOPK - 1];
            int bud = TOPK;
            #pragma unroll
            for (int s = 0; s < S; ++s) bud -= (sc[ch][s] > thr);
            const int slot = w0 + ch + R;
            float sum = 0.0f, mx = -3.0e38f;
            #pragma unroll
            for (int s = 0; s < S; ++s) {
                const float v = sm[(s * SLOTS + slot) * P + hw];
                mx = fmaxf(mx, v);
                bool tk = sc[ch][s] > thr;
                if (sc[ch][s] == thr && bud > 0) { tk = true; --bud; }
                if (tk) sum += v;
            }
            const int c = it * CI + 2 * cg + ch;
            out[(n * C + c) * HW + hw0 + hw] =
                alpha * (sum * (1.0f / TOPK)) + (1.0f - alpha) * mx;
        }
        __syncthreads();   // tile reads done before next iteration overwrites
    }
}

extern "C" void kernel_launch(void* const* d_in, const int* in_sizes, int n_in,
                              void* d_out, int out_size) {
    const float* seqs  = (const float*)d_in[0];
    const float* logit = (const float*)d_in[1];
    float* out = (float*)d_out;
    cudaFuncSetAttribute(kfused, cudaFuncAttributeMaxDynamicSharedMemorySize, SMEMB);
    kinit<<<R + 1, 128>>>();
    kfused<<<dim3(HW / H, N), 256, SMEMB>>>(seqs, logit, out);
}

// round 11
// speedup vs baseline: 1.7598x; 1.7598x over previous
#include <cuda_runtime.h>
#include <cstdint>

constexpr int N = 64, C = 256, S = 30, HW = 176;
constexpr int CSTR = S * HW, NSTR = C * CSTR;
constexpr int R = 8, TOPK = 10;
constexpr int H = 8;                      // hw per block: 32B rows, sector-aligned
constexpr int CI = 64, NIT = 4;           // channels per iteration
constexpr int SLOTS = CI + 2 * R;         // 80 (circular halo)
constexpr int P = 12;                     // pitch words: 8 hw + 4 pad, conflict-free
constexpr int SCH = 10, NCH = 3;          // s-chunks for load/compute overlap
// Trim unreachable tail padding of the last row so 2 blocks fit in 227KB/SM.
constexpr int SMEMW = S * SLOTS * P - (P - H);
constexpr int SMEMB = SMEMW * 4;          // 115184 B -> 2 blocks/SM

__device__ float d_g[R + 1];

// g[d] = (1/256)(1 + 2*sum_{k=1..127} e^{-k^2/2048} cos(pi k d/128) + e^{-8} cos(pi d))
__global__ void kinit() {
    const int d = blockIdx.x, t = threadIdx.x;
    const double PI = 3.14159265358979323846;
    double k = (double)(t + 1);
    double term = exp(-k * k / 2048.0) * cos(PI * k * (double)d / 128.0);
    if (t != 127) term *= 2.0;            // Nyquist (k=128) counted once
    __shared__ double red[4];
    #pragma unroll
    for (int o = 16; o; o >>= 1) term += __shfl_down_sync(0xffffffffu, term, o);
    if ((t & 31) == 0) red[t >> 5] = term;
    __syncthreads();
    if (t == 0) d_g[d] = (float)((1.0 + red[0] + red[1] + red[2] + red[3]) / 256.0);
}

__global__ void __launch_bounds__(256, 2)
kfused(const float* __restrict__ seqs, const float* __restrict__ flogit,
       float* __restrict__ out) {
    extern __shared__ float sm[];
    const int hw0 = blockIdx.x * H;
    const int n   = blockIdx.y;
    const int tid = threadIdx.x;
    const int hw  = tid & 7;
    const int cg  = tid >> 3;             // 0..31 -> local channels 2cg, 2cg+1
    const int w0  = 2 * cg;               // window base slot
    const float alpha = 1.0f / (1.0f + expf(-flogit[0]));

    float g[R + 1];
    #pragma unroll
    for (int d = 0; d <= R; ++d) g[d] = d_g[d];

    #pragma unroll 1
    for (int it = 0; it < NIT; ++it) {
        const int cb = it * CI + C - R;   // slot -> channel (cb+slot)&255

        // Issue all 3 s-chunk load groups (two 16B cp.asyncs per 32B row;
        // pitch-12 rows are 48B-spaced -> both 16B-aligned)
        #pragma unroll
        for (int ck = 0; ck < NCH; ++ck) {
            for (int i = tid; i < SLOTS * SCH * 2; i += 256) {
                int q = i & 1, r = i >> 1;
                int sl = r / SLOTS, slot = r - sl * SLOTS;
                int s = ck * SCH + sl;
                int c = (cb + slot) & 255;
                const float* src = seqs + (size_t)n * NSTR + (size_t)c * CSTR
                                   + s * HW + hw0 + q * 4;
                uint32_t dst = (uint32_t)__cvta_generic_to_shared(
                    sm + (s * SLOTS + slot) * P + q * 4);
                asm volatile("cp.async.cg.shared.global [%0],[%1],16;"
                             :: "r"(dst), "l"(src));
            }
            asm volatile("cp.async.commit_group;" ::: "memory");
        }

        float sc[2][S], top[2][TOPK];
        #pragma unroll
        for (int ch = 0; ch < 2; ++ch)
            #pragma unroll
            for (int i = 0; i < TOPK; ++i) top[ch][i] = -1.0f;

        // Compute chunk k while chunk k+1 streams in
        #pragma unroll
        for (int ck = 0; ck < NCH; ++ck) {
            if (ck == 0)      asm volatile("cp.async.wait_group 2;" ::: "memory");
            else if (ck == 1) asm volatile("cp.async.wait_group 1;" ::: "memory");
            else              asm volatile("cp.async.wait_group 0;" ::: "memory");
            __syncthreads();

            #pragma unroll
            for (int j = 0; j < SCH; ++j) {
                const int s = ck * SCH + j;
                const float* b = sm + (s * SLOTS + w0) * P + hw;
                float w[2 * R + 2];
                #pragma unroll
                for (int u = 0; u < 2 * R + 2; ++u) w[u] = b[u * P];
                #pragma unroll
                for (int ch = 0; ch < 2; ++ch) {
                    const float x = w[ch + R];
                    float acc = g[0] * x;
                    #pragma unroll
                    for (int d = 1; d <= R; ++d)
                        acc = fmaf(g[d], w[ch + R - d] + w[ch + R + d], acc);
                    const float sv = __fdividef(fabsf(acc), fabsf(acc - x) + 1e-6f);
                    sc[ch][s] = sv;
                    float cr = sv;             // triangular insertion chain
                    #pragma unroll
                    for (int i = 0; i < TOPK; ++i) {
                        if (i <= s) {
                            float m = fmaxf(top[ch][i], cr);
                            cr      = fminf(top[ch][i], cr);
                            top[ch][i] = m;
                        }
                    }
                }
            }
        }

        // Threshold + stable-tie selection + max pool + fused output
        #pragma unroll
        for (int ch = 0; ch < 2; ++ch) {
            const float thr = top[ch][TOPK - 1];
            int bud = TOPK;
            #pragma unroll
            for (int s = 0; s < S; ++s) bud -= (sc[ch][s] > thr);
            const int slot = w0 + ch + R;
            float sum = 0.0f, mx = -3.0e38f;
            #pragma unroll
            for (int s = 0; s < S; ++s) {
                const float v = sm[(s * SLOTS + slot) * P + hw];
                mx = fmaxf(mx, v);
                bool tk = sc[ch][s] > thr;
                if (sc[ch][s] == thr && bud > 0) { tk = true; --bud; }
                if (tk) sum += v;
            }
            const int c = it * CI + 2 * cg + ch;
            out[(n * C + c) * HW + hw0 + hw] =
                alpha * (sum * (1.0f / TOPK)) + (1.0f - alpha) * mx;
        }
        __syncthreads();   // tile reads done before next iteration overwrites
    }
}

extern "C" void kernel_launch(void* const* d_in, const int* in_sizes, int n_in,
                              void* d_out, int out_size) {
    const float* seqs  = (const float*)d_in[0];
    const float* logit = (const float*)d_in[1];
    float* out = (float*)d_out;
    cudaFuncSetAttribute(kfused, cudaFuncAttributeMaxDynamicSharedMemorySize, SMEMB);
    kinit<<<R + 1, 128>>>();
    kfused<<<dim3(HW / H, N), 256, SMEMB>>>(seqs, logit, out);
}